// round 4
// baseline (speedup 1.0000x reference)
#include <cuda_runtime.h>
#include <cuda_bf16.h>
#include <math.h>

// Problem constants: x [16, 256, 128, 128] fp32, w [1, 2, 7, 7] fp32
// out [16, 1, 128, 128] fp32
#define B_  16
#define C_  256
#define H_  128
#define W_  128
#define HW_ (H_ * W_)          // 16384
#define HW4_ (HW_ / 4)         // 4096 float4 groups per plane

// Scratch: s = [B, 2, H, W] -> mean plane then max plane per batch. 2 MB.
__device__ float g_s[B_ * 2 * HW_];

// ---------------------------------------------------------------------------
// Kernel 1: channel-wise mean + max. One thread = 4 spatial pixels (float4).
// 65536 threads total. Reads 268 MB -> HBM bound.
// ---------------------------------------------------------------------------
__global__ __launch_bounds__(256) void reduce_mean_max_kernel(const float* __restrict__ x) {
    int t = blockIdx.x * blockDim.x + threadIdx.x;   // 0 .. 65535
    int b   = t >> 12;        // / 4096
    int sp4 = t & 4095;       // float4 group within plane

    const float4* base = reinterpret_cast<const float4*>(x) + (size_t)b * C_ * HW4_ + sp4;

    float4 sum = make_float4(0.f, 0.f, 0.f, 0.f);
    float4 mx  = make_float4(-INFINITY, -INFINITY, -INFINITY, -INFINITY);

    #pragma unroll 8
    for (int c = 0; c < C_; ++c) {
        float4 v = __ldg(base + c * HW4_);
        sum.x += v.x; sum.y += v.y; sum.z += v.z; sum.w += v.w;
        mx.x = fmaxf(mx.x, v.x); mx.y = fmaxf(mx.y, v.y);
        mx.z = fmaxf(mx.z, v.z); mx.w = fmaxf(mx.w, v.w);
    }

    const float inv = 1.0f / (float)C_;
    float4 avg = make_float4(sum.x * inv, sum.y * inv, sum.z * inv, sum.w * inv);

    float4* s_mean = reinterpret_cast<float4*>(g_s) + (size_t)b * 2 * HW4_ + sp4;
    float4* s_max  = s_mean + HW4_;
    *s_mean = avg;
    *s_max  = mx;
}

// ---------------------------------------------------------------------------
// Kernel 2: 7x7 'same' conv (2 in-ch: mean, max) + sigmoid.
// One thread per output pixel. s (2 MB) lives in L2; weights in L1.
// ---------------------------------------------------------------------------
__global__ __launch_bounds__(256) void conv_sigmoid_kernel(const float* __restrict__ wgt,
                                                           float* __restrict__ out) {
    int t = blockIdx.x * blockDim.x + threadIdx.x;   // 0 .. 262143
    int b  = t >> 14;        // / 16384
    int hw = t & 16383;
    int h  = hw >> 7;        // / 128
    int w  = hw & 127;

    const float* s0 = g_s + (size_t)b * 2 * HW_;   // mean plane
    const float* s1 = s0 + HW_;                    // max plane

    float acc = 0.0f;
    #pragma unroll
    for (int kh = 0; kh < 7; ++kh) {
        int hh = h + kh - 3;
        if ((unsigned)hh >= (unsigned)H_) continue;
        const float* r0 = s0 + hh * W_;
        const float* r1 = s1 + hh * W_;
        #pragma unroll
        for (int kw = 0; kw < 7; ++kw) {
            int ww = w + kw - 3;
            if ((unsigned)ww >= (unsigned)W_) continue;
            float w0 = __ldg(wgt + kh * 7 + kw);        // in-channel 0 (mean)
            float w1 = __ldg(wgt + 49 + kh * 7 + kw);   // in-channel 1 (max)
            acc = fmaf(__ldg(r0 + ww), w0, acc);
            acc = fmaf(__ldg(r1 + ww), w1, acc);
        }
    }

    out[t] = 1.0f / (1.0f + __expf(-acc));
}

extern "C" void kernel_launch(void* const* d_in, const int* in_sizes, int n_in,
                              void* d_out, int out_size) {
    const float* x = (const float*)d_in[0];
    const float* w = (const float*)d_in[1];
    float* out = (float*)d_out;

    // Kernel 1: 65536 threads (one per float4 of 4 pixels)
    reduce_mean_max_kernel<<<(B_ * HW4_) / 256, 256>>>(x);

    // Kernel 2: 262144 threads (one per output pixel)
    conv_sigmoid_kernel<<<(B_ * HW_) / 256, 256>>>(w, out);
}

// round 5
// speedup vs baseline: 1.1517x; 1.1517x over previous
#include <cuda_runtime.h>
#include <cuda_bf16.h>
#include <math.h>

// Problem constants: x [16, 256, 128, 128] fp32, w [1, 2, 7, 7] fp32
// out [16, 1, 128, 128] fp32
#define B_  16
#define C_  256
#define H_  128
#define W_  128
#define HW_ (H_ * W_)          // 16384
#define HW4_ (HW_ / 4)         // 4096 float4 groups per plane
#define NCHUNK 4
#define CPC (C_ / NCHUNK)      // 64 channels per chunk

// Scratch.
// g_part: per-chunk partial [chunk][B][2][HW]  (sum plane, max plane) = 8 MB
// g_s:    combined          [B][2][HW]                               = 2 MB
__device__ float g_part[NCHUNK * B_ * 2 * HW_];
__device__ float g_s[B_ * 2 * HW_];

// ---------------------------------------------------------------------------
// Kernel 1: partial channel sum + max over a 64-channel chunk.
// 1024 blocks (6.9 waves over 148 SMs) -> good wave balance + deep MLP.
// ---------------------------------------------------------------------------
__global__ __launch_bounds__(256) void reduce_partial_kernel(const float* __restrict__ x) {
    int chunk = blockIdx.x >> 8;                       // 0..3
    int t = ((blockIdx.x & 255) << 8) + threadIdx.x;   // 0..65535
    int b   = t >> 12;        // / 4096
    int sp4 = t & 4095;       // float4 group within plane

    const float4* base = reinterpret_cast<const float4*>(x)
                       + (size_t)b * C_ * HW4_ + (size_t)chunk * CPC * HW4_ + sp4;

    float4 sum = make_float4(0.f, 0.f, 0.f, 0.f);
    float4 mx  = make_float4(-INFINITY, -INFINITY, -INFINITY, -INFINITY);

    #pragma unroll 8
    for (int c = 0; c < CPC; ++c) {
        float4 v = __ldg(base + c * HW4_);
        sum.x += v.x; sum.y += v.y; sum.z += v.z; sum.w += v.w;
        mx.x = fmaxf(mx.x, v.x); mx.y = fmaxf(mx.y, v.y);
        mx.z = fmaxf(mx.z, v.z); mx.w = fmaxf(mx.w, v.w);
    }

    float4* p_sum = reinterpret_cast<float4*>(g_part)
                  + (size_t)chunk * B_ * 2 * HW4_ + (size_t)b * 2 * HW4_ + sp4;
    float4* p_max = p_sum + HW4_;
    *p_sum = sum;
    *p_max = mx;
}

// ---------------------------------------------------------------------------
// Kernel 2: combine 4 chunk partials -> mean & max planes. L2-resident, ~2us.
// ---------------------------------------------------------------------------
__global__ __launch_bounds__(256) void combine_kernel() {
    int t = blockIdx.x * blockDim.x + threadIdx.x;     // 0..65535
    int b   = t >> 12;
    int sp4 = t & 4095;

    const float4* base = reinterpret_cast<const float4*>(g_part)
                       + (size_t)b * 2 * HW4_ + sp4;
    const size_t cs = (size_t)B_ * 2 * HW4_;           // chunk stride in float4

    float4 sum = make_float4(0.f, 0.f, 0.f, 0.f);
    float4 mx  = make_float4(-INFINITY, -INFINITY, -INFINITY, -INFINITY);
    #pragma unroll
    for (int k = 0; k < NCHUNK; ++k) {
        float4 s = base[k * cs];
        float4 m = base[k * cs + HW4_];
        sum.x += s.x; sum.y += s.y; sum.z += s.z; sum.w += s.w;
        mx.x = fmaxf(mx.x, m.x); mx.y = fmaxf(mx.y, m.y);
        mx.z = fmaxf(mx.z, m.z); mx.w = fmaxf(mx.w, m.w);
    }
    const float inv = 1.0f / (float)C_;
    float4 avg = make_float4(sum.x * inv, sum.y * inv, sum.z * inv, sum.w * inv);

    float4* s_mean = reinterpret_cast<float4*>(g_s) + (size_t)b * 2 * HW4_ + sp4;
    *s_mean = avg;
    *(s_mean + HW4_) = mx;
}

// ---------------------------------------------------------------------------
// Kernel 3: 7x7 conv (2ch) + sigmoid, 4-wide register blocking.
// Each thread: 4 horizontal pixels from 3 float4 loads/row/channel.
// 42 LDG + 98 broadcast LDS + 392 FMA per thread -> fma/issue bound (~3us).
// ---------------------------------------------------------------------------
__global__ __launch_bounds__(256) void conv_sigmoid_kernel(const float* __restrict__ wgt,
                                                           float* __restrict__ out) {
    __shared__ float ws[98];
    if (threadIdx.x < 98) ws[threadIdx.x] = __ldg(wgt + threadIdx.x);
    __syncthreads();

    int t = blockIdx.x * blockDim.x + threadIdx.x;     // 0..65535 (one per 4 pixels)
    int b   = t >> 12;
    int sp4 = t & 4095;
    int h   = sp4 >> 5;           // 0..127
    int g   = sp4 & 31;           // float4 group in row, 0..31

    const float4 z4 = make_float4(0.f, 0.f, 0.f, 0.f);
    float acc0 = 0.f, acc1 = 0.f, acc2 = 0.f, acc3 = 0.f;

    #pragma unroll
    for (int ch = 0; ch < 2; ++ch) {
        const float* sp = g_s + ((size_t)b * 2 + ch) * HW_;
        const float* wp = ws + ch * 49;
        #pragma unroll
        for (int kh = 0; kh < 7; ++kh) {
            int hh = h + kh - 3;
            if ((unsigned)hh >= (unsigned)H_) continue;
            const float4* row = reinterpret_cast<const float4*>(sp + hh * W_);
            float4 lo  = (g > 0)  ? row[g - 1] : z4;
            float4 mid = row[g];
            float4 hi  = (g < 31) ? row[g + 1] : z4;
            float v[12] = { lo.x, lo.y, lo.z, lo.w,
                            mid.x, mid.y, mid.z, mid.w,
                            hi.x, hi.y, hi.z, hi.w };
            #pragma unroll
            for (int kw = 0; kw < 7; ++kw) {
                float wv = wp[kh * 7 + kw];
                // input col = w0 + j + kw - 3 ; array offset = 4 + (j + kw - 3)
                acc0 = fmaf(v[kw + 1], wv, acc0);
                acc1 = fmaf(v[kw + 2], wv, acc1);
                acc2 = fmaf(v[kw + 3], wv, acc2);
                acc3 = fmaf(v[kw + 4], wv, acc3);
            }
        }
    }

    float4 r;
    r.x = 1.0f / (1.0f + __expf(-acc0));
    r.y = 1.0f / (1.0f + __expf(-acc1));
    r.z = 1.0f / (1.0f + __expf(-acc2));
    r.w = 1.0f / (1.0f + __expf(-acc3));
    reinterpret_cast<float4*>(out)[t] = r;
}

extern "C" void kernel_launch(void* const* d_in, const int* in_sizes, int n_in,
                              void* d_out, int out_size) {
    const float* x = (const float*)d_in[0];
    const float* w = (const float*)d_in[1];
    float* out = (float*)d_out;

    reduce_partial_kernel<<<NCHUNK * 256, 256>>>(x);   // 1024 blocks
    combine_kernel<<<256, 256>>>();
    conv_sigmoid_kernel<<<256, 256>>>(w, out);
}

// round 8
// speedup vs baseline: 1.2527x; 1.0877x over previous
#include <cuda_runtime.h>
#include <cuda_bf16.h>
#include <math.h>

// Problem constants: x [16, 256, 128, 128] fp32, w [1, 2, 7, 7] fp32
// out [16, 1, 128, 128] fp32
#define B_  16
#define C_  256
#define H_  128
#define W_  128
#define HW_ (H_ * W_)          // 16384
#define HW4_ (HW_ / 4)         // 4096 float4 groups per plane
#define NCHUNK 4
#define CPC (C_ / NCHUNK)      // 64 channels per chunk
#define TH  8                  // output rows per conv tile
#define TR  (TH + 6)           // input rows per tile (halo +-3)

// Scratch: per-chunk partials [chunk][B][2][HW] (sum plane, max plane) = 8 MB
__device__ float g_part[NCHUNK * B_ * 2 * HW_];

// ---------------------------------------------------------------------------
// Kernel 1: partial channel sum + max over a 64-channel chunk.
// 1024 blocks = one full wave at occ 8 blocks/SM. __ldcs keeps the 268 MB
// stream from evicting the 8 MB partials out of L2.
// ---------------------------------------------------------------------------
__global__ __launch_bounds__(256) void reduce_partial_kernel(const float* __restrict__ x) {
    int chunk = blockIdx.x >> 8;                       // 0..3
    int t = ((blockIdx.x & 255) << 8) + threadIdx.x;   // 0..65535
    int b   = t >> 12;        // / 4096
    int sp4 = t & 4095;       // float4 group within plane

    const float4* base = reinterpret_cast<const float4*>(x)
                       + (size_t)b * C_ * HW4_ + (size_t)chunk * CPC * HW4_ + sp4;

    float4 sum = make_float4(0.f, 0.f, 0.f, 0.f);
    float4 mx  = make_float4(-INFINITY, -INFINITY, -INFINITY, -INFINITY);

    #pragma unroll 8
    for (int c = 0; c < CPC; ++c) {
        float4 v = __ldcs(base + c * HW4_);            // streaming, evict-first
        sum.x += v.x; sum.y += v.y; sum.z += v.z; sum.w += v.w;
        mx.x = fmaxf(mx.x, v.x); mx.y = fmaxf(mx.y, v.y);
        mx.z = fmaxf(mx.z, v.z); mx.w = fmaxf(mx.w, v.w);
    }

    float4* p_sum = reinterpret_cast<float4*>(g_part)
                  + (size_t)chunk * B_ * 2 * HW4_ + (size_t)b * 2 * HW4_ + sp4;
    float4* p_max = p_sum + HW4_;
    *p_sum = sum;
    *p_max = mx;
}

// ---------------------------------------------------------------------------
// Kernel 2 (fused): combine 4 chunk partials -> mean/max tile in smem (with
// vertical halo, zero padded), then 7x7 2-ch conv + sigmoid, 4-wide register
// blocked. 256 blocks x 256 threads; each block = 8 output rows of one batch.
// ---------------------------------------------------------------------------
__global__ __launch_bounds__(256) void fused_combine_conv_kernel(const float* __restrict__ wgt,
                                                                 float* __restrict__ out) {
    __shared__ float4 sm[2][TR][32];   // [plane][input row][float4 group]  14 KB
    __shared__ float  ws[98];

    if (threadIdx.x < 98) ws[threadIdx.x] = __ldg(wgt + threadIdx.x);

    int b    = blockIdx.x >> 4;        // batch
    int tile = blockIdx.x & 15;        // 16 tiles of TH rows
    int h0   = tile * TH;              // first output row
    int r0   = h0 - 3;                 // first input row (may be < 0)

    const size_t cs = (size_t)B_ * 2 * HW4_;   // chunk stride in float4
    const float inv = 1.0f / (float)C_;
    const float4* pb = reinterpret_cast<const float4*>(g_part) + (size_t)b * 2 * HW4_;

    // Combine phase: 2 planes x TR rows x 32 groups = 896 float4 items.
    // Plane boundary is at 448 (= TR*32) -> exact division, NOT a shift.
    for (int i = threadIdx.x; i < 2 * TR * 32; i += 256) {
        int plane = i / (TR * 32);           // 0 or 1 (boundary 448)
        int rem   = i - plane * (TR * 32);
        int r     = rem >> 5;
        int g     = rem & 31;
        int hh    = r0 + r;

        float4 v = make_float4(0.f, 0.f, 0.f, 0.f);
        if ((unsigned)hh < (unsigned)H_) {
            const float4* p = pb + (size_t)plane * HW4_ + hh * 32 + g;
            if (plane == 0) {
                float4 s0 = p[0], s1 = p[cs], s2 = p[2*cs], s3 = p[3*cs];
                v.x = (s0.x + s1.x + s2.x + s3.x) * inv;
                v.y = (s0.y + s1.y + s2.y + s3.y) * inv;
                v.z = (s0.z + s1.z + s2.z + s3.z) * inv;
                v.w = (s0.w + s1.w + s2.w + s3.w) * inv;
            } else {
                float4 m0 = p[0], m1 = p[cs], m2 = p[2*cs], m3 = p[3*cs];
                v.x = fmaxf(fmaxf(m0.x, m1.x), fmaxf(m2.x, m3.x));
                v.y = fmaxf(fmaxf(m0.y, m1.y), fmaxf(m2.y, m3.y));
                v.z = fmaxf(fmaxf(m0.z, m1.z), fmaxf(m2.z, m3.z));
                v.w = fmaxf(fmaxf(m0.w, m1.w), fmaxf(m2.w, m3.w));
            }
        }
        sm[plane][r][g] = v;
    }
    __syncthreads();

    // Conv phase: thread -> (output row r, group g); 8 rows x 32 groups = 256
    int g = threadIdx.x & 31;
    int r = threadIdx.x >> 5;              // 0..7

    float acc0 = 0.f, acc1 = 0.f, acc2 = 0.f, acc3 = 0.f;
    const float4 z4 = make_float4(0.f, 0.f, 0.f, 0.f);

    #pragma unroll
    for (int ch = 0; ch < 2; ++ch) {
        const float* wp = ws + ch * 49;
        #pragma unroll
        for (int kh = 0; kh < 7; ++kh) {
            // input row index in smem = r + kh  (global row h0 + r - 3 + kh)
            float4 lo  = (g > 0)  ? sm[ch][r + kh][g - 1] : z4;
            float4 mid = sm[ch][r + kh][g];
            float4 hi  = (g < 31) ? sm[ch][r + kh][g + 1] : z4;
            float v[12] = { lo.x, lo.y, lo.z, lo.w,
                            mid.x, mid.y, mid.z, mid.w,
                            hi.x, hi.y, hi.z, hi.w };
            #pragma unroll
            for (int kw = 0; kw < 7; ++kw) {
                float wv = wp[kh * 7 + kw];
                acc0 = fmaf(v[kw + 1], wv, acc0);
                acc1 = fmaf(v[kw + 2], wv, acc1);
                acc2 = fmaf(v[kw + 3], wv, acc2);
                acc3 = fmaf(v[kw + 4], wv, acc3);
            }
        }
    }

    float4 res;
    res.x = 1.0f / (1.0f + __expf(-acc0));
    res.y = 1.0f / (1.0f + __expf(-acc1));
    res.z = 1.0f / (1.0f + __expf(-acc2));
    res.w = 1.0f / (1.0f + __expf(-acc3));
    reinterpret_cast<float4*>(out)[(size_t)b * HW4_ + (h0 + r) * 32 + g] = res;
}

extern "C" void kernel_launch(void* const* d_in, const int* in_sizes, int n_in,
                              void* d_out, int out_size) {
    const float* x = (const float*)d_in[0];
    const float* w = (const float*)d_in[1];
    float* out = (float*)d_out;

    reduce_partial_kernel<<<NCHUNK * 256, 256>>>(x);        // 1024 blocks
    fused_combine_conv_kernel<<<B_ * (H_ / TH), 256>>>(w, out);  // 256 blocks
}